// round 7
// baseline (speedup 1.0000x reference)
#include <cuda_runtime.h>
#include <cstdint>

// Fixed shapes: B=16, K=64, H=96, W=96
constexpr int B = 16;
constexpr int K = 64;
constexpr int H = 96;
constexpr int W = 96;
constexpr int IMG = H * W;                      // 9216
constexpr int NSTACK = B * K;                   // 1024
constexpr long long NBIG = (long long)B * K * H * W;
constexpr int KP_ELEMS = B * 3 * K * 2;         // 6144
constexpr int ZETA_ELEMS = B * K;               // 1024

constexpr int THREADS = 256;                    // 8 warps
constexpr int NCHUNK = 3;                       // 3 chunks of 32 rows
constexpr int CH_ROWS  = H / NCHUNK;            // 32
constexpr int CH_ELEMS = CH_ROWS * W;           // 3072 floats
constexpr int CH_BYTES = CH_ELEMS * 4;          // 12288 B
constexpr int CH_V4    = CH_ELEMS / 4;          // 768 float4
constexpr int CH_ITERS = CH_V4 / THREADS;       // 3

// sigmoid with div.approx (MUFU.RCP + FMUL) instead of div.rn's ~8-instr
// expansion. rel err ~2e-7, still ~4 decades under the 1e-3 gate.
__device__ __forceinline__ float sigmoidf(float x) {
    return __fdividef(1.0f, 1.0f + __expf(-x));
}

// mbarrier wait with HW sleep hint — no hot-spin issue theft
__device__ __forceinline__ void mbar_wait(uint32_t msa, uint32_t parity) {
    uint32_t done;
    asm volatile(
        "{\n\t.reg .pred p;\n\t"
        "mbarrier.try_wait.parity.acquire.cta.shared::cta.b64 p, [%1], %2;\n\t"
        "selp.b32 %0, 1, 0, p;\n\t}"
        : "=r"(done) : "r"(msa), "r"(parity) : "memory");
    if (!done) {
        asm volatile(
            "{\n\t.reg .pred P1;\n\t"
            "WAIT_LOOP_%=:\n\t"
            "mbarrier.try_wait.parity.acquire.cta.shared::cta.b64 P1, [%0], %1, 0x989680;\n\t"
            "@P1 bra.uni WAIT_DONE_%=;\n\t"
            "bra.uni WAIT_LOOP_%=;\n\t"
            "WAIT_DONE_%=:\n\t}"
            :: "r"(msa), "r"(parity) : "memory");
    }
}

__global__ __launch_bounds__(THREADS)
void fused_decode_kernel(const float* __restrict__ Rk,
                         const float* __restrict__ tfRk,
                         float* __restrict__ Dk_out,
                         float* __restrict__ tfDk_out,
                         float* __restrict__ kp_out,
                         float* __restrict__ tfkp_out,
                         float* __restrict__ zeta_out,
                         float* __restrict__ tfzeta_out)
{
    __shared__ alignas(128) float buf[NCHUNK][CH_ELEMS];   // 3 x 12 KB, written once each
    __shared__ alignas(8) unsigned long long mbar[NCHUNK];
    __shared__ float sm0[8], smx[8], smy[8];

    const int stack = blockIdx.x;                 // 0..1023
    const int which = blockIdx.y;                 // 0 = Rk, 1 = tf_Rk
    const int tid = threadIdx.x;
    const int lane = tid & 31;
    const int warp = tid >> 5;

    const float* __restrict__ R  = (which == 0 ? Rk : tfRk) + (size_t)stack * IMG;
    float* __restrict__ D        = (which == 0 ? Dk_out : tfDk_out) + (size_t)stack * IMG;
    float* __restrict__ kp_base  = (which == 0 ? kp_out : tfkp_out);
    float* __restrict__ zeta_base = (which == 0 ? zeta_out : tfzeta_out);

    if (tid < NCHUNK) {
        const uint32_t msa = (uint32_t)__cvta_generic_to_shared(&mbar[tid]);
        asm volatile("mbarrier.init.shared.b64 [%0], %1;" :: "r"(msa), "r"(1) : "memory");
    }
    __syncthreads();

    // Fire all chunk TMAs upfront: full 36 KB in flight, compute starts as
    // soon as the first 12 KB lands. One mbarrier per chunk, used once.
    if (tid == 0) {
#pragma unroll
        for (int c = 0; c < NCHUNK; ++c) {
            const uint32_t msa = (uint32_t)__cvta_generic_to_shared(&mbar[c]);
            const uint32_t bsa = (uint32_t)__cvta_generic_to_shared(&buf[c][0]);
            const float* src = R + c * CH_ELEMS;
            asm volatile("mbarrier.arrive.expect_tx.shared.b64 _, [%0], %1;"
                         :: "r"(msa), "r"(CH_BYTES) : "memory");
            asm volatile("cp.async.bulk.shared::cta.global.mbarrier::complete_tx::bytes "
                         "[%0], [%1], %2, [%3];"
                         :: "r"(bsa), "l"(src), "r"(CH_BYTES), "r"(msa) : "memory");
        }
    }

    float s0 = 0.0f, sx = 0.0f, sy = 0.0f;

#pragma unroll
    for (int c = 0; c < NCHUNK; ++c) {
        mbar_wait((uint32_t)__cvta_generic_to_shared(&mbar[c]), 0u);

        const float4* __restrict__ T4 = reinterpret_cast<const float4*>(&buf[c][0]);
        float4* __restrict__ D4 = reinterpret_cast<float4*>(D) + c * CH_V4;

#pragma unroll
        for (int it = 0; it < CH_ITERS; ++it) {
            const int v = tid + it * THREADS;     // float4 index within chunk [0,768)
            float4 r = T4[v];
            float4 d;
            d.x = sigmoidf(r.x);
            d.y = sigmoidf(r.y);
            d.z = sigmoidf(r.z);
            d.w = sigmoidf(r.w);
            D4[v] = d;

            const int e = v * 4;
            const int hl = e / W;                 // local row within chunk
            const int w = e - hl * W;
            const int h = hl + c * CH_ROWS;       // global row
            const float rowsum = (d.x + d.y) + (d.z + d.w);
            s0 += rowsum;
            sy += rowsum * (float)h;
            sx += fmaf((float)w, rowsum, fmaf(3.0f, d.w, fmaf(2.0f, d.z, d.y)));
        }
    }

    // ---- block reduction ----
#pragma unroll
    for (int o = 16; o > 0; o >>= 1) {
        s0 += __shfl_down_sync(0xffffffffu, s0, o);
        sx += __shfl_down_sync(0xffffffffu, sx, o);
        sy += __shfl_down_sync(0xffffffffu, sy, o);
    }
    if (lane == 0) { sm0[warp] = s0; smx[warp] = sx; smy[warp] = sy; }
    __syncthreads();

    if (tid == 0) {
        float z = 0.0f, fx = 0.0f, fy = 0.0f;
#pragma unroll
        for (int i = 0; i < 8; ++i) { z += sm0[i]; fx += smx[i]; fy += smy[i]; }

        // NOTE: the division here must stay full-precision (div.rn) — kx/ky
        // feed rintf and a 1-ulp error at a .5 boundary would flip a pixel.
        const float kx = rintf(fx / z);
        const float ky = rintf(fy / z);
        const int wi = (int)kx;
        const int hi = (int)ky;

        // d at rounded location: buffers never recycled -> read from smem.
        // Use the precise sigmoid form here to match the map values closely.
        const int ch = hi / CH_ROWS;
        const float rv = buf[ch][(hi - ch * CH_ROWS) * W + wi];
        const float dloc = 1.0f / (1.0f + __expf(-rv));

        const int b = stack / K;
        const int k = stack - b * K;

        float* kp  = kp_base + ((size_t)b * (3 * K) + k) * 2;
        float* kp1 = kp_base + ((size_t)b * (3 * K) + K + k) * 2;
        float* kp2 = kp_base + ((size_t)b * (3 * K) + 2 * K + k) * 2;
        kp[0]  = kx;
        kp[1]  = ky;
        kp1[0] = truncf(kx + kx * dloc);
        kp1[1] = truncf(ky + ky * dloc);
        kp2[0] = truncf(kx - kx * dloc);
        kp2[1] = truncf(ky - ky * dloc);

        zeta_base[stack] = z;
    }
}

extern "C" void kernel_launch(void* const* d_in, const int* in_sizes, int n_in,
                              void* d_out, int out_size)
{
    const float* Rk   = (const float*)d_in[0];
    const float* tfRk = (const float*)d_in[1];

    float* out = (float*)d_out;
    float* Dk     = out;
    float* tfDk   = out + NBIG;
    float* kp     = out + 2 * NBIG;
    float* tfkp   = kp + KP_ELEMS;
    float* zeta   = tfkp + KP_ELEMS;
    float* tfzeta = zeta + ZETA_ELEMS;

    dim3 grid(NSTACK, 2);
    fused_decode_kernel<<<grid, THREADS>>>(Rk, tfRk, Dk, tfDk, kp, tfkp, zeta, tfzeta);
}

// round 10
// speedup vs baseline: 1.0721x; 1.0721x over previous
#include <cuda_runtime.h>
#include <cstdint>

// Fixed shapes: B=16, K=64, H=96, W=96
constexpr int B = 16;
constexpr int K = 64;
constexpr int H = 96;
constexpr int W = 96;
constexpr int IMG = H * W;                      // 9216
constexpr int NSTACK = B * K;                   // 1024
constexpr long long NBIG = (long long)B * K * H * W;
constexpr int KP_ELEMS = B * 3 * K * 2;         // 6144
constexpr int ZETA_ELEMS = B * K;               // 1024

constexpr int THREADS = 256;                    // 8 warps
constexpr int NCHUNK = 3;                       // 3 chunks of 32 rows
constexpr int CH_ROWS  = H / NCHUNK;            // 32
constexpr int CH_ELEMS = CH_ROWS * W;           // 3072 floats
constexpr int CH_BYTES = CH_ELEMS * 4;          // 12288 B
constexpr int CH_V4    = CH_ELEMS / 4;          // 768 float4
constexpr int CH_ITERS = CH_V4 / THREADS;       // 3

// sigmoid with div.approx (MUFU.RCP + FMUL); rel err ~2e-7 << 1e-3 gate
__device__ __forceinline__ float sigmoidf(float x) {
    return __fdividef(1.0f, 1.0f + __expf(-x));
}

// mbarrier wait with HW sleep hint — no hot-spin issue theft
__device__ __forceinline__ void mbar_wait(uint32_t msa, uint32_t parity) {
    uint32_t done;
    asm volatile(
        "{\n\t.reg .pred p;\n\t"
        "mbarrier.try_wait.parity.acquire.cta.shared::cta.b64 p, [%1], %2;\n\t"
        "selp.b32 %0, 1, 0, p;\n\t}"
        : "=r"(done) : "r"(msa), "r"(parity) : "memory");
    if (!done) {
        asm volatile(
            "{\n\t.reg .pred P1;\n\t"
            "WAIT_LOOP_%=:\n\t"
            "mbarrier.try_wait.parity.acquire.cta.shared::cta.b64 P1, [%0], %1, 0x989680;\n\t"
            "@P1 bra.uni WAIT_DONE_%=;\n\t"
            "bra.uni WAIT_LOOP_%=;\n\t"
            "WAIT_DONE_%=:\n\t}"
            :: "r"(msa), "r"(parity) : "memory");
    }
}

__global__ __launch_bounds__(THREADS)
void fused_decode_kernel(const float* __restrict__ Rk,
                         const float* __restrict__ tfRk,
                         float* __restrict__ Dk_out,
                         float* __restrict__ tfDk_out,
                         float* __restrict__ kp_out,
                         float* __restrict__ tfkp_out,
                         float* __restrict__ zeta_out,
                         float* __restrict__ tfzeta_out)
{
    __shared__ alignas(128) float buf[NCHUNK][CH_ELEMS];   // 3 x 12 KB, written once each
    __shared__ alignas(8) unsigned long long mbar[NCHUNK];
    __shared__ float sm0[8], smx[8], smy[8];

    const int stack = blockIdx.x;                 // 0..1023
    const int which = blockIdx.y;                 // 0 = Rk, 1 = tf_Rk
    const int tid = threadIdx.x;
    const int lane = tid & 31;
    const int warp = tid >> 5;

    const float* __restrict__ R  = (which == 0 ? Rk : tfRk) + (size_t)stack * IMG;
    float* __restrict__ D        = (which == 0 ? Dk_out : tfDk_out) + (size_t)stack * IMG;
    float* __restrict__ kp_base  = (which == 0 ? kp_out : tfkp_out);
    float* __restrict__ zeta_base = (which == 0 ? zeta_out : tfzeta_out);

    if (tid < NCHUNK) {
        const uint32_t msa = (uint32_t)__cvta_generic_to_shared(&mbar[tid]);
        asm volatile("mbarrier.init.shared.b64 [%0], %1;" :: "r"(msa), "r"(1) : "memory");
    }
    __syncthreads();

    // L2 policies: input reads = evict_first (compulsory DRAM traffic each
    // replay, must not displace pinned output); output stores = evict_last
    // (write-only, rewritten every replay -> keep resident in L2).
    uint64_t pol_ef, pol_el;
    asm volatile("createpolicy.fractional.L2::evict_first.b64 %0, 1.0;" : "=l"(pol_ef));
    asm volatile("createpolicy.fractional.L2::evict_last.b64 %0, 1.0;"  : "=l"(pol_el));

    // Fire all chunk TMAs upfront: 36 KB in flight, compute starts as soon
    // as the first 12 KB lands.
    if (tid == 0) {
#pragma unroll
        for (int c = 0; c < NCHUNK; ++c) {
            const uint32_t msa = (uint32_t)__cvta_generic_to_shared(&mbar[c]);
            const uint32_t bsa = (uint32_t)__cvta_generic_to_shared(&buf[c][0]);
            const float* src = R + c * CH_ELEMS;
            asm volatile("mbarrier.arrive.expect_tx.shared.b64 _, [%0], %1;"
                         :: "r"(msa), "r"(CH_BYTES) : "memory");
            asm volatile("cp.async.bulk.shared::cta.global.mbarrier::complete_tx::bytes.L2::cache_hint "
                         "[%0], [%1], %2, [%3], %4;"
                         :: "r"(bsa), "l"(src), "r"(CH_BYTES), "r"(msa), "l"(pol_ef)
                         : "memory");
        }
    }

    float s0 = 0.0f, sx = 0.0f, sy = 0.0f;

#pragma unroll
    for (int c = 0; c < NCHUNK; ++c) {
        mbar_wait((uint32_t)__cvta_generic_to_shared(&mbar[c]), 0u);

        const float4* __restrict__ T4 = reinterpret_cast<const float4*>(&buf[c][0]);
        float4* __restrict__ D4 = reinterpret_cast<float4*>(D) + c * CH_V4;

#pragma unroll
        for (int it = 0; it < CH_ITERS; ++it) {
            const int v = tid + it * THREADS;     // float4 index within chunk [0,768)
            float4 r = T4[v];
            float4 d;
            d.x = sigmoidf(r.x);
            d.y = sigmoidf(r.y);
            d.z = sigmoidf(r.z);
            d.w = sigmoidf(r.w);

            // Heatmap store with evict_last policy operand (cache_hint form —
            // no width restriction, unlike the bare .L2::evict_last modifier).
            asm volatile("st.global.L2::cache_hint.v4.f32 [%0], {%1, %2, %3, %4}, %5;"
                         :: "l"(D4 + v), "f"(d.x), "f"(d.y), "f"(d.z), "f"(d.w),
                            "l"(pol_el)
                         : "memory");

            const int e = v * 4;
            const int hl = e / W;                 // local row within chunk
            const int w = e - hl * W;
            const int h = hl + c * CH_ROWS;       // global row
            const float rowsum = (d.x + d.y) + (d.z + d.w);
            s0 += rowsum;
            sy += rowsum * (float)h;
            sx += fmaf((float)w, rowsum, fmaf(3.0f, d.w, fmaf(2.0f, d.z, d.y)));
        }
    }

    // ---- block reduction ----
#pragma unroll
    for (int o = 16; o > 0; o >>= 1) {
        s0 += __shfl_down_sync(0xffffffffu, s0, o);
        sx += __shfl_down_sync(0xffffffffu, sx, o);
        sy += __shfl_down_sync(0xffffffffu, sy, o);
    }
    if (lane == 0) { sm0[warp] = s0; smx[warp] = sx; smy[warp] = sy; }
    __syncthreads();

    if (tid == 0) {
        float z = 0.0f, fx = 0.0f, fy = 0.0f;
#pragma unroll
        for (int i = 0; i < 8; ++i) { z += sm0[i]; fx += smx[i]; fy += smy[i]; }

        // Full-precision div here: kx/ky feed rintf; a 1-ulp error at a .5
        // boundary would flip a pixel.
        const float kx = rintf(fx / z);
        const float ky = rintf(fy / z);
        const int wi = (int)kx;
        const int hi = (int)ky;

        // d at rounded location: buffers never recycled -> read from smem.
        const int ch = hi / CH_ROWS;
        const float rv = buf[ch][(hi - ch * CH_ROWS) * W + wi];
        const float dloc = 1.0f / (1.0f + __expf(-rv));

        const int b = stack / K;
        const int k = stack - b * K;

        float* kp  = kp_base + ((size_t)b * (3 * K) + k) * 2;
        float* kp1 = kp_base + ((size_t)b * (3 * K) + K + k) * 2;
        float* kp2 = kp_base + ((size_t)b * (3 * K) + 2 * K + k) * 2;
        kp[0]  = kx;
        kp[1]  = ky;
        kp1[0] = truncf(kx + kx * dloc);
        kp1[1] = truncf(ky + ky * dloc);
        kp2[0] = truncf(kx - kx * dloc);
        kp2[1] = truncf(ky - ky * dloc);

        zeta_base[stack] = z;
    }
}

extern "C" void kernel_launch(void* const* d_in, const int* in_sizes, int n_in,
                              void* d_out, int out_size)
{
    const float* Rk   = (const float*)d_in[0];
    const float* tfRk = (const float*)d_in[1];

    float* out = (float*)d_out;
    float* Dk     = out;
    float* tfDk   = out + NBIG;
    float* kp     = out + 2 * NBIG;
    float* tfkp   = kp + KP_ELEMS;
    float* zeta   = tfkp + KP_ELEMS;
    float* tfzeta = zeta + ZETA_ELEMS;

    dim3 grid(NSTACK, 2);
    fused_decode_kernel<<<grid, THREADS>>>(Rk, tfRk, Dk, tfDk, kp, tfkp, zeta, tfzeta);
}

// round 11
// speedup vs baseline: 1.1475x; 1.0704x over previous
#include <cuda_runtime.h>
#include <cstdint>

// Fixed shapes: B=16, K=64, H=96, W=96
constexpr int B = 16;
constexpr int K = 64;
constexpr int H = 96;
constexpr int W = 96;
constexpr int IMG = H * W;                      // 9216
constexpr int NSTACK = B * K;                   // 1024
constexpr long long NBIG = (long long)B * K * H * W;
constexpr int KP_ELEMS = B * 3 * K * 2;         // 6144
constexpr int ZETA_ELEMS = B * K;               // 1024

constexpr int THREADS = 256;                    // 8 warps
constexpr int NCHUNK = 3;                       // 3 chunks of 32 rows
constexpr int CH_ROWS  = H / NCHUNK;            // 32
constexpr int CH_ELEMS = CH_ROWS * W;           // 3072 floats
constexpr int CH_BYTES = CH_ELEMS * 4;          // 12288 B
constexpr int CH_V4    = CH_ELEMS / 4;          // 768 float4
constexpr int CH_ITERS = CH_V4 / THREADS;       // 3

// sigmoid with div.approx (MUFU.RCP + FMUL); rel err ~2e-7 << 1e-3 gate
__device__ __forceinline__ float sigmoidf(float x) {
    return __fdividef(1.0f, 1.0f + __expf(-x));
}

// mbarrier wait with HW sleep hint — no hot-spin issue theft
__device__ __forceinline__ void mbar_wait(uint32_t msa, uint32_t parity) {
    uint32_t done;
    asm volatile(
        "{\n\t.reg .pred p;\n\t"
        "mbarrier.try_wait.parity.acquire.cta.shared::cta.b64 p, [%1], %2;\n\t"
        "selp.b32 %0, 1, 0, p;\n\t}"
        : "=r"(done) : "r"(msa), "r"(parity) : "memory");
    if (!done) {
        asm volatile(
            "{\n\t.reg .pred P1;\n\t"
            "WAIT_LOOP_%=:\n\t"
            "mbarrier.try_wait.parity.acquire.cta.shared::cta.b64 P1, [%0], %1, 0x989680;\n\t"
            "@P1 bra.uni WAIT_DONE_%=;\n\t"
            "bra.uni WAIT_LOOP_%=;\n\t"
            "WAIT_DONE_%=:\n\t}"
            :: "r"(msa), "r"(parity) : "memory");
    }
}

__global__ __launch_bounds__(THREADS)
void fused_decode_kernel(const float* __restrict__ Rk,
                         const float* __restrict__ tfRk,
                         float* __restrict__ Dk_out,
                         float* __restrict__ tfDk_out,
                         float* __restrict__ kp_out,
                         float* __restrict__ tfkp_out,
                         float* __restrict__ zeta_out,
                         float* __restrict__ tfzeta_out)
{
    __shared__ alignas(128) float buf[NCHUNK][CH_ELEMS];   // 3 x 12 KB
    __shared__ alignas(8) unsigned long long mbar[NCHUNK];
    __shared__ float sm0[8], smx[8], smy[8];

    const int stack = blockIdx.x;                 // 0..1023
    const int which = blockIdx.y;                 // 0 = Rk, 1 = tf_Rk
    const int tid = threadIdx.x;
    const int lane = tid & 31;
    const int warp = tid >> 5;

    const float* __restrict__ R  = (which == 0 ? Rk : tfRk) + (size_t)stack * IMG;
    float* __restrict__ D        = (which == 0 ? Dk_out : tfDk_out) + (size_t)stack * IMG;
    float* __restrict__ kp_base  = (which == 0 ? kp_out : tfkp_out);
    float* __restrict__ zeta_base = (which == 0 ? zeta_out : tfzeta_out);

    if (tid < NCHUNK) {
        const uint32_t msa = (uint32_t)__cvta_generic_to_shared(&mbar[tid]);
        asm volatile("mbarrier.init.shared.b64 [%0], %1;" :: "r"(msa), "r"(1) : "memory");
    }
    __syncthreads();

    // L2 policies: input reads = evict_first; output writes = evict_last
    // (write-only output rewritten every graph replay -> keep resident in L2).
    uint64_t pol_ef, pol_el;
    asm volatile("createpolicy.fractional.L2::evict_first.b64 %0, 1.0;" : "=l"(pol_ef));
    asm volatile("createpolicy.fractional.L2::evict_last.b64 %0, 1.0;"  : "=l"(pol_el));

    // Fire all chunk TMA loads upfront: 36 KB in flight immediately.
    if (tid == 0) {
#pragma unroll
        for (int c = 0; c < NCHUNK; ++c) {
            const uint32_t msa = (uint32_t)__cvta_generic_to_shared(&mbar[c]);
            const uint32_t bsa = (uint32_t)__cvta_generic_to_shared(&buf[c][0]);
            const float* src = R + c * CH_ELEMS;
            asm volatile("mbarrier.arrive.expect_tx.shared.b64 _, [%0], %1;"
                         :: "r"(msa), "r"(CH_BYTES) : "memory");
            asm volatile("cp.async.bulk.shared::cta.global.mbarrier::complete_tx::bytes.L2::cache_hint "
                         "[%0], [%1], %2, [%3], %4;"
                         :: "r"(bsa), "l"(src), "r"(CH_BYTES), "r"(msa), "l"(pol_ef)
                         : "memory");
        }
    }

    float s0 = 0.0f, sx = 0.0f, sy = 0.0f;

#pragma unroll
    for (int c = 0; c < NCHUNK; ++c) {
        mbar_wait((uint32_t)__cvta_generic_to_shared(&mbar[c]), 0u);

        float4* __restrict__ T4 = reinterpret_cast<float4*>(&buf[c][0]);

        // Sigmoid IN PLACE in smem (STS, no L1 wavefronts, no scoreboard),
        // moments accumulated from registers.
#pragma unroll
        for (int it = 0; it < CH_ITERS; ++it) {
            const int v = tid + it * THREADS;     // float4 index within chunk [0,768)
            float4 r = T4[v];
            float4 d;
            d.x = sigmoidf(r.x);
            d.y = sigmoidf(r.y);
            d.z = sigmoidf(r.z);
            d.w = sigmoidf(r.w);
            T4[v] = d;                            // overwrite input with sigmoid

            const int e = v * 4;
            const int hl = e / W;                 // local row within chunk
            const int w = e - hl * W;
            const int h = hl + c * CH_ROWS;       // global row
            const float rowsum = (d.x + d.y) + (d.z + d.w);
            s0 += rowsum;
            sy += rowsum * (float)h;
            sx += fmaf((float)w, rowsum, fmaf(3.0f, d.w, fmaf(2.0f, d.z, d.y)));
        }

        // Chunk fully converted in smem -> one bulk TMA store (async, bypasses
        // the per-thread L1 store path, carries the evict_last pin).
        __syncthreads();
        if (tid == 0) {
            const uint32_t bsa = (uint32_t)__cvta_generic_to_shared(&buf[c][0]);
            float* dst = D + c * CH_ELEMS;
            asm volatile("fence.proxy.async.shared::cta;" ::: "memory");
            asm volatile("cp.async.bulk.global.shared::cta.bulk_group.L2::cache_hint "
                         "[%0], [%1], %2, %3;"
                         :: "l"(dst), "r"(bsa), "r"(CH_BYTES), "l"(pol_el)
                         : "memory");
            asm volatile("cp.async.bulk.commit_group;" ::: "memory");
        }
    }

    // ---- block reduction ----
#pragma unroll
    for (int o = 16; o > 0; o >>= 1) {
        s0 += __shfl_down_sync(0xffffffffu, s0, o);
        sx += __shfl_down_sync(0xffffffffu, sx, o);
        sy += __shfl_down_sync(0xffffffffu, sy, o);
    }
    if (lane == 0) { sm0[warp] = s0; smx[warp] = sx; smy[warp] = sy; }
    __syncthreads();

    if (tid == 0) {
        float z = 0.0f, fx = 0.0f, fy = 0.0f;
#pragma unroll
        for (int i = 0; i < 8; ++i) { z += sm0[i]; fx += smx[i]; fy += smy[i]; }

        // Full-precision div: kx/ky feed rintf; 1-ulp at a .5 boundary flips a pixel.
        const float kx = rintf(fx / z);
        const float ky = rintf(fy / z);
        const int wi = (int)kx;
        const int hi = (int)ky;

        // smem now holds the SIGMOIDED map -> dloc is a direct read.
        const int ch = hi / CH_ROWS;
        const float dloc = buf[ch][(hi - ch * CH_ROWS) * W + wi];

        const int b = stack / K;
        const int k = stack - b * K;

        float* kp  = kp_base + ((size_t)b * (3 * K) + k) * 2;
        float* kp1 = kp_base + ((size_t)b * (3 * K) + K + k) * 2;
        float* kp2 = kp_base + ((size_t)b * (3 * K) + 2 * K + k) * 2;
        kp[0]  = kx;
        kp[1]  = ky;
        kp1[0] = truncf(kx + kx * dloc);
        kp1[1] = truncf(ky + ky * dloc);
        kp2[0] = truncf(kx - kx * dloc);
        kp2[1] = truncf(ky - ky * dloc);

        zeta_base[stack] = z;

        // Drain outstanding bulk stores before block exit.
        asm volatile("cp.async.bulk.wait_group 0;" ::: "memory");
    }
}

extern "C" void kernel_launch(void* const* d_in, const int* in_sizes, int n_in,
                              void* d_out, int out_size)
{
    const float* Rk   = (const float*)d_in[0];
    const float* tfRk = (const float*)d_in[1];

    float* out = (float*)d_out;
    float* Dk     = out;
    float* tfDk   = out + NBIG;
    float* kp     = out + 2 * NBIG;
    float* tfkp   = kp + KP_ELEMS;
    float* zeta   = tfkp + KP_ELEMS;
    float* tfzeta = zeta + ZETA_ELEMS;

    dim3 grid(NSTACK, 2);
    fused_decode_kernel<<<grid, THREADS>>>(Rk, tfRk, Dk, tfDk, kp, tfkp, zeta, tfzeta);
}